// round 6
// baseline (speedup 1.0000x reference)
#include <cuda_runtime.h>
#include <math.h>

#define BB 64
#define TT 256
#define FF 64
#define UU 512
#define GG 2048      // 4*UU
#define NBLK 128
#define NTHR 512
#define CU 4         // units per block
#define NC 16        // gate-columns per block (4 gates x 4 units)
#define WS2 514      // rec dup-weight row stride (float2 units, even -> 16B aligned)
#define WXS2 66      // x dup-weight row stride (float2 units)

// ---- static device scratch (no cudaMalloc anywhere) ----
__device__ float g_hsT[(size_t)TT * UU * BB]; // all h: [(t*512+u)*64 + b]
__device__ float g_coef[TT];
__device__ float g_shift[TT];
__device__ float g_sumW;
__device__ unsigned g_cnt = 0;
__device__ volatile unsigned g_gen = 0;       // monotonic across launches

__device__ __forceinline__ float sigmoidf_(float x) { return 1.f / (1.f + expf(-x)); }

// packed fp32x2 FMA (Blackwell)
__device__ __forceinline__ unsigned long long fma2(unsigned long long a,
                                                   unsigned long long b,
                                                   unsigned long long c) {
    unsigned long long d;
    asm("fma.rn.f32x2 %0, %1, %2, %3;" : "=l"(d) : "l"(a), "l"(b), "l"(c));
    return d;
}
__device__ __forceinline__ unsigned long long pack2(float v) {
    unsigned long long p;
    unsigned u = __float_as_uint(v);
    asm("mov.b64 %0, {%1, %1};" : "=l"(p) : "r"(u));
    return p;
}

__device__ __forceinline__ void grid_barrier() {
    __threadfence();
    __syncthreads();
    if (threadIdx.x == 0) {
        unsigned gen = g_gen;
        if (atomicAdd(&g_cnt, 1u) == (unsigned)(NBLK - 1)) {
            g_cnt = 0u;
            __threadfence();
            g_gen = gen + 1u;
        } else {
            while (g_gen == gen) { }
        }
    }
    __syncthreads();
}

// no-op pad so ncu's fixed capture slot (-s 5) lands on lstm_persist
__global__ void pad_kernel() {}

// ---------------------------------------------------------------------------
// prep (parallel): block t<TT computes coef/shift; block TT reduces out_W.
// ---------------------------------------------------------------------------
__global__ void prep_kernel(const float* __restrict__ attW,
                            const float* __restrict__ attb,
                            const float* __restrict__ outW)
{
    __shared__ float red[256];
    int tid = threadIdx.x;
    if (blockIdx.x < TT) {
        int t = blockIdx.x;
        float s = 0.f;
        for (int j = tid; j < t; j += 256) s += attW[t * TT + j];
        red[tid] = s;
        __syncthreads();
        for (int off = 128; off > 0; off >>= 1) {
            if (tid < off) red[tid] += red[tid + off];
            __syncthreads();
        }
        if (tid == 0) {
            g_coef[t]  = (t == 0) ? 1.f : red[0];
            g_shift[t] = (t == 0) ? 0.f : attb[t];
        }
    } else {
        red[tid] = outW[tid] + outW[tid + 256];
        __syncthreads();
        for (int off = 128; off > 0; off >>= 1) {
            if (tid < off) red[tid] += red[tid + off];
            __syncthreads();
        }
        if (tid == 0) g_sumW = red[0];
    }
}

// ---------------------------------------------------------------------------
// Persistent LSTM. 128 blocks, 512 threads (4 warps/SMSP, 4-way split-K).
// Block owns 4 units (16 gate cols). Thread tile: 2 cols x 4 batches
// (4 indep f32x2 chains), k-quarter kq of K=512.
// h read straight from L2 via LDG.128 (fresh address slice every step ->
// no staging, no chunk syncs). Weights resident in smem as duplicated f32x2;
// loaded as LDS.128 covering 2 k.
// ---------------------------------------------------------------------------
// smem (floats):
//   sWd  [16][514 f32x2]  = 16448
//   sWxd [16][66 f32x2]   =  2112
//   sx2  [64][64]         =  4096
//   sg   [4][16][68]      =  4352
#define OFF_SW   0
#define OFF_SWX  (NC * WS2 * 2)
#define OFF_SX   (OFF_SWX + NC * WXS2 * 2)
#define OFF_SG   (OFF_SX + FF * BB)
#define SMEM_FLOATS (OFF_SG + 4 * NC * 68)

__global__ void __launch_bounds__(NTHR, 1)
lstm_persist(const float* __restrict__ x,     // (B,T,F)
             const float* __restrict__ Wk,    // (F,4U)
             const float* __restrict__ Rk,    // (U,4U)
             const float* __restrict__ bias)  // (4U)
{
    extern __shared__ float smem[];
    float* sWd  = smem + OFF_SW;
    float* sWxd = smem + OFF_SWX;
    float* sx2  = smem + OFF_SX;
    float* sg   = smem + OFF_SG;

    const int tid = threadIdx.x;
    const int bid = blockIdx.x;
    const int u0  = bid * CU;

    // ---- one-time weight staging, duplicated f32x2 ----
    for (int idx = tid; idx < UU * NC; idx += NTHR) {
        int k = idx >> 4, c = idx & 15;
        int gcol = (c >> 2) * UU + u0 + (c & 3);
        float w = Rk[(size_t)k * GG + gcol];
        ((float2*)sWd)[c * WS2 + k] = make_float2(w, w);
    }
    for (int idx = tid; idx < FF * NC; idx += NTHR) {
        int f = idx >> 4, c = idx & 15;
        int gcol = (c >> 2) * UU + u0 + (c & 3);
        float w = Wk[(size_t)f * GG + gcol];
        ((float2*)sWxd)[c * WXS2 + f] = make_float2(w, w);
    }

    // GEMM identity: k-quarter kq, cols {cg, cg+8}, batches [b0, b0+4)
    const int kq   = tid >> 7;            // 0..3
    const int gtid = tid & 127;
    const int cg   = gtid & 7;
    const int b0   = ((gtid >> 3) & 15) << 2;
    const int c0 = cg, c1 = cg + 8;
    const int kbase = kq * 128;           // k range [kbase, kbase+128)
    const unsigned long long bp0 =
        (kq == 0) ? pack2(bias[(c0 >> 2) * UU + u0 + (c0 & 3)]) : 0ull;
    const unsigned long long bp1 =
        (kq == 0) ? pack2(bias[(c1 >> 2) * UU + u0 + (c1 & 3)]) : 0ull;

    const float2* w0row = (const float2*)sWd + c0 * WS2 + kbase;
    const float2* w1row = (const float2*)sWd + c1 * WS2 + kbase;
    const float2* wx0   = (const float2*)sWxd + c0 * WXS2 + kq * 16;
    const float2* wx1   = (const float2*)sWxd + c1 * WXS2 + kq * 16;

    // pointwise identity (tid < 256): unit pj, batch pb
    const int pj = (tid >> 6) & 3;
    const int pb = tid & 63;
    float creg = 0.f;

    __syncthreads();

    for (int t = 0; t < TT; ++t) {
        // ---- stage x_t transposed: sx2[f*64 + b] ----
        for (int i = tid; i < (BB * FF) / 4; i += NTHR) {   // 2 iters/thread
            int b  = i & 63;
            int f0 = (i >> 6) << 2;
            float4 xv = *(const float4*)(x + ((size_t)b * TT + t) * FF + f0);
            sx2[(f0 + 0) * 64 + b] = xv.x;
            sx2[(f0 + 1) * 64 + b] = xv.y;
            sx2[(f0 + 2) * 64 + b] = xv.z;
            sx2[(f0 + 3) * 64 + b] = xv.w;
        }
        __syncthreads();

        unsigned long long a00 = bp0, a01 = bp0;  // col c0
        unsigned long long a10 = bp1, a11 = bp1;  // col c1

        // ---- input projection: this quarter's 16 f ----
        {
            const float* sxq = sx2 + (kq * 16) * 64 + b0;
            #pragma unroll 4
            for (int f2 = 0; f2 < 16; f2 += 2) {
                ulonglong2 w0p = *(const ulonglong2*)(wx0 + f2);
                ulonglong2 w1p = *(const ulonglong2*)(wx1 + f2);
                ulonglong2 xa = *(const ulonglong2*)(sxq + (f2 + 0) * 64);
                ulonglong2 xb = *(const ulonglong2*)(sxq + (f2 + 1) * 64);
                a00 = fma2(xa.x, w0p.x, a00); a01 = fma2(xa.y, w0p.x, a01);
                a10 = fma2(xa.x, w1p.x, a10); a11 = fma2(xa.y, w1p.x, a11);
                a00 = fma2(xb.x, w0p.y, a00); a01 = fma2(xb.y, w0p.y, a01);
                a10 = fma2(xb.x, w1p.y, a10); a11 = fma2(xb.y, w1p.y, a11);
            }
        }

        // ---- recurrent projection: this quarter's 128 k, h via LDG.128 ----
        if (t > 0) {
            const float* hk = g_hsT + ((size_t)(t - 1) * UU + kbase) * BB + b0;
            #pragma unroll 4
            for (int k2 = 0; k2 < 128; k2 += 2) {
                ulonglong2 w0p = *(const ulonglong2*)(w0row + k2);
                ulonglong2 w1p = *(const ulonglong2*)(w1row + k2);
                ulonglong2 ha = *(const ulonglong2*)(hk + (size_t)(k2 + 0) * 64);
                ulonglong2 hb = *(const ulonglong2*)(hk + (size_t)(k2 + 1) * 64);
                a00 = fma2(ha.x, w0p.x, a00); a01 = fma2(ha.y, w0p.x, a01);
                a10 = fma2(ha.x, w1p.x, a10); a11 = fma2(ha.y, w1p.x, a11);
                a00 = fma2(hb.x, w0p.y, a00); a01 = fma2(hb.y, w0p.y, a01);
                a10 = fma2(hb.x, w1p.y, a10); a11 = fma2(hb.y, w1p.y, a11);
            }
        }

        // ---- write partial gate sums: sg[kq][c][b] ----
        float* sgk = sg + kq * NC * 68;
        *(ulonglong2*)(sgk + c0 * 68 + b0) = make_ulonglong2(a00, a01);
        *(ulonglong2*)(sgk + c1 * 68 + b0) = make_ulonglong2(a10, a11);
        __syncthreads();

        // ---- pointwise (tid < 256): sum 4 partials, update c, write h ----
        if (tid < 256) {
            float iv = 0.f, fv = 0.f, gv = 0.f, ov = 0.f;
            #pragma unroll
            for (int q = 0; q < 4; ++q) {
                const float* sq = sg + q * NC * 68;
                iv += sq[(0 * 4 + pj) * 68 + pb];
                fv += sq[(1 * 4 + pj) * 68 + pb];
                gv += sq[(2 * 4 + pj) * 68 + pb];
                ov += sq[(3 * 4 + pj) * 68 + pb];
            }
            creg = sigmoidf_(fv) * creg + sigmoidf_(iv) * tanhf(gv);
            float hval = sigmoidf_(ov) * tanhf(creg);
            g_hsT[((size_t)t * UU + u0 + pj) * 64 + pb] = hval;
        }

        grid_barrier();
    }
}

// ---------------------------------------------------------------------------
// Output: y[b,t] = sigmoid(coef[t] * <h_bt, out_W> + shift[t]*sumW + out_b)
// ---------------------------------------------------------------------------
__global__ void out_kernel(const float* __restrict__ outW,
                           const float* __restrict__ outb,
                           float* __restrict__ y)
{
    int t  = blockIdx.x;
    int b  = threadIdx.x & 63;
    int ug = threadIdx.x >> 6;   // 0..3
    float s = 0.f;
    const float* base = g_hsT + (size_t)t * UU * BB;
    #pragma unroll 4
    for (int u = ug * 128; u < ug * 128 + 128; ++u)
        s += base[(size_t)u * 64 + b] * outW[u];
    __shared__ float red[4][64];
    red[ug][b] = s;
    __syncthreads();
    if (ug == 0) {
        float v = red[0][b] + red[1][b] + red[2][b] + red[3][b];
        v = g_coef[t] * v + g_shift[t] * g_sumW + outb[0];
        y[b * TT + t] = 1.f / (1.f + expf(-v));
    }
}

// ---------------------------------------------------------------------------
extern "C" void kernel_launch(void* const* d_in, const int* in_sizes, int n_in,
                              void* d_out, int out_size)
{
    (void)in_sizes; (void)n_in; (void)out_size;
    const float* inputs = (const float*)d_in[0];
    const float* kernel = (const float*)d_in[1];
    const float* rec    = (const float*)d_in[2];
    const float* bias   = (const float*)d_in[3];
    const float* attW   = (const float*)d_in[4];
    const float* attb   = (const float*)d_in[5];
    const float* outW   = (const float*)d_in[6];
    const float* outb   = (const float*)d_in[7];
    float* y = (float*)d_out;

    static int smem_set = 0;
    size_t smem_bytes = SMEM_FLOATS * sizeof(float);   // ~108 KB
    if (!smem_set) {
        cudaFuncSetAttribute(lstm_persist,
                             cudaFuncAttributeMaxDynamicSharedMemorySize,
                             (int)smem_bytes);
        smem_set = 1;
    }

    // two pads so lstm_persist lands on ncu's capture slot (-s 5)
    pad_kernel<<<1, 32>>>();
    pad_kernel<<<1, 32>>>();
    prep_kernel<<<TT + 1, 256>>>(attW, attb, outW);
    lstm_persist<<<NBLK, NTHR, smem_bytes>>>(inputs, kernel, rec, bias);
    out_kernel<<<TT, 256>>>(outW, outb, y);
}

// round 7
// speedup vs baseline: 1.1192x; 1.1192x over previous
#include <cuda_runtime.h>
#include <math.h>

#define BB 64
#define TT 256
#define FF 64
#define UU 512
#define GG 2048      // 4*UU
#define NBLK 128
#define NTHR 256
#define CU 4         // units per block
#define NC 16        // gate-columns per block
#define NW 8         // warps (k split 8 ways)
#define KW 64        // k per warp

// ---- static device scratch (no cudaMalloc anywhere) ----
__device__ float g_hsT[(size_t)TT * UU * BB]; // all h: [(t*512+u)*64 + b]
__device__ float g_coef[TT];
__device__ float g_shift[TT];
__device__ float g_sumW;
__device__ unsigned g_cnt = 0;
__device__ volatile unsigned g_gen = 0;       // monotonic across launches

__device__ __forceinline__ float sigmoidf_(float x) { return 1.f / (1.f + expf(-x)); }

// packed fp32x2 FMA (Blackwell)
__device__ __forceinline__ unsigned long long fma2(unsigned long long a,
                                                   unsigned long long b,
                                                   unsigned long long c) {
    unsigned long long d;
    asm("fma.rn.f32x2 %0, %1, %2, %3;" : "=l"(d) : "l"(a), "l"(b), "l"(c));
    return d;
}

__device__ __forceinline__ void grid_barrier() {
    __threadfence();
    __syncthreads();
    if (threadIdx.x == 0) {
        unsigned gen = g_gen;
        if (atomicAdd(&g_cnt, 1u) == (unsigned)(NBLK - 1)) {
            g_cnt = 0u;
            __threadfence();
            g_gen = gen + 1u;
        } else {
            while (g_gen == gen) { }
        }
    }
    __syncthreads();
}

// no-op pads so ncu's fixed capture slot (-s 5) lands on lstm_persist
__global__ void pad_kernel() {}

// ---------------------------------------------------------------------------
__global__ void prep_kernel(const float* __restrict__ attW,
                            const float* __restrict__ attb,
                            const float* __restrict__ outW)
{
    __shared__ float red[256];
    int tid = threadIdx.x;
    if (blockIdx.x < TT) {
        int t = blockIdx.x;
        float s = 0.f;
        for (int j = tid; j < t; j += 256) s += attW[t * TT + j];
        red[tid] = s;
        __syncthreads();
        for (int off = 128; off > 0; off >>= 1) {
            if (tid < off) red[tid] += red[tid + off];
            __syncthreads();
        }
        if (tid == 0) {
            g_coef[t]  = (t == 0) ? 1.f : red[0];
            g_shift[t] = (t == 0) ? 0.f : attb[t];
        }
    } else {
        red[tid] = outW[tid] + outW[tid + 256];
        __syncthreads();
        for (int off = 128; off > 0; off >>= 1) {
            if (tid < off) red[tid] += red[tid + off];
            __syncthreads();
        }
        if (tid == 0) g_sumW = red[0];
    }
}

// ---------------------------------------------------------------------------
// Persistent LSTM. 128 blocks, 256 threads (8 warps, k split 8 ways).
// Warp covers the full 16-col x 64-batch tile for its 64 k.
// Thread tile: 4 cols x 8 batches = 16 f32x2 accumulators.
// Weights dup'd f32x2, quad-packed: w2[k][cq*4+j] = dup w of col (cq + 4j)
//   -> thread's 4 cols contiguous: 2 LDS.128 per k.
// h via LDG.128 straight from L2 (fresh slice each step), prefetch dist 1.
// ---------------------------------------------------------------------------
// smem (floats):
//   w2  [512][16] f32x2 = 16384 f (64 KB)
//   wx2 [64][16]  f32x2 =  2048 f (8 KB)
//   sx2 [64][64]        =  4096 f (16 KB)
//   sg  [8][16][68]     =  8704 f (34 KB)
#define OFF_W2   0
#define OFF_WX2  (UU * NC * 2)
#define OFF_SX   (OFF_WX2 + FF * NC * 2)
#define OFF_SG   (OFF_SX + FF * BB)
#define SMEM_FLOATS (OFF_SG + NW * NC * 68)

__global__ void __launch_bounds__(NTHR, 1)
lstm_persist(const float* __restrict__ x,     // (B,T,F)
             const float* __restrict__ Wk,    // (F,4U)
             const float* __restrict__ Rk,    // (U,4U)
             const float* __restrict__ bias)  // (4U)
{
    extern __shared__ float smem[];
    float* w2  = smem + OFF_W2;    // f32x2 pairs
    float* wx2 = smem + OFF_WX2;
    float* sx2 = smem + OFF_SX;
    float* sg  = smem + OFF_SG;

    const int tid = threadIdx.x;
    const int bid = blockIdx.x;
    const int u0  = bid * CU;

    // ---- one-time weight staging (dup'd f32x2, quad-packed cols) ----
    for (int idx = tid; idx < UU * NC; idx += NTHR) {
        int k = idx >> 4, m = idx & 15;
        int c = (m >> 2) + ((m & 3) << 2);          // col for slot m
        int gcol = (c >> 2) * UU + u0 + (c & 3);
        float w = Rk[(size_t)k * GG + gcol];
        ((float2*)w2)[k * 16 + m] = make_float2(w, w);
    }
    for (int idx = tid; idx < FF * NC; idx += NTHR) {
        int f = idx >> 4, m = idx & 15;
        int c = (m >> 2) + ((m & 3) << 2);
        int gcol = (c >> 2) * UU + u0 + (c & 3);
        float w = Wk[(size_t)f * GG + gcol];
        ((float2*)wx2)[f * 16 + m] = make_float2(w, w);
    }

    // GEMM identity
    const int wid  = tid >> 5;        // warp 0..7 -> k range [wid*64, ..)
    const int lane = tid & 31;
    const int cq   = lane >> 3;       // 0..3: cols {cq, cq+4, cq+8, cq+12}
    const int bo   = lane & 7;        // 0..7: batches [bo*8, bo*8+8)
    const int kb   = wid * KW;
    const int b0   = bo * 8;

    // pointwise identity: unit pj, batch pb; bias preloaded
    const int pj = tid >> 6;          // 0..3
    const int pb = tid & 63;
    const float bi0 = bias[0 * UU + u0 + pj];
    const float bi1 = bias[1 * UU + u0 + pj];
    const float bi2 = bias[2 * UU + u0 + pj];
    const float bi3 = bias[3 * UU + u0 + pj];
    float creg = 0.f;

    __syncthreads();

    for (int t = 0; t < TT; ++t) {
        // ---- stage x_t transposed: sx2[f*64 + b] ----
        for (int i = tid; i < (BB * FF) / 4; i += NTHR) {
            int b  = i & 63;
            int f0 = (i >> 6) << 2;
            float4 xv = *(const float4*)(x + ((size_t)b * TT + t) * FF + f0);
            sx2[(f0 + 0) * 64 + b] = xv.x;
            sx2[(f0 + 1) * 64 + b] = xv.y;
            sx2[(f0 + 2) * 64 + b] = xv.z;
            sx2[(f0 + 3) * 64 + b] = xv.w;
        }
        __syncthreads();

        // accumulators: [col j][batch pair p]
        unsigned long long a[4][4];
        #pragma unroll
        for (int j = 0; j < 4; ++j)
            #pragma unroll
            for (int p = 0; p < 4; ++p) a[j][p] = 0ull;

        // ---- input projection: this warp's 8 f ----
        {
            const float* xp = sx2 + (wid * 8) * 64 + b0;
            const ulonglong2* wxp =
                (const ulonglong2*)((float2*)wx2 + (size_t)(wid * 8) * 16 + cq * 4);
            #pragma unroll
            for (int f = 0; f < 8; ++f) {
                ulonglong2 xa = *(const ulonglong2*)(xp + f * 64);
                ulonglong2 xb = *(const ulonglong2*)(xp + f * 64 + 4);
                ulonglong2 wa = wxp[f * 8];
                ulonglong2 wb = wxp[f * 8 + 1];
                unsigned long long wv;
                #pragma unroll
                for (int j = 0; j < 4; ++j) {
                    wv = (j == 0) ? wa.x : (j == 1) ? wa.y : (j == 2) ? wb.x : wb.y;
                    a[j][0] = fma2(xa.x, wv, a[j][0]);
                    a[j][1] = fma2(xa.y, wv, a[j][1]);
                    a[j][2] = fma2(xb.x, wv, a[j][2]);
                    a[j][3] = fma2(xb.y, wv, a[j][3]);
                }
            }
        }

        // ---- recurrent projection: this warp's 64 k, h via LDG.128 ----
        if (t > 0) {
            const float* hp = g_hsT + ((size_t)(t - 1) * UU + kb) * BB + b0;
            const ulonglong2* wp =
                (const ulonglong2*)((float2*)w2 + (size_t)kb * 16 + cq * 4);

            ulonglong2 ha = *(const ulonglong2*)hp;
            ulonglong2 hb = *(const ulonglong2*)(hp + 4);
            ulonglong2 wa = wp[0];
            ulonglong2 wb = wp[1];

            #pragma unroll 4
            for (int k = 0; k < KW; ++k) {
                ulonglong2 ha_n, hb_n, wa_n, wb_n;
                if (k + 1 < KW) {
                    const float* hn = hp + (size_t)(k + 1) * 64;
                    ha_n = *(const ulonglong2*)hn;
                    hb_n = *(const ulonglong2*)(hn + 4);
                    wa_n = wp[(k + 1) * 8];
                    wb_n = wp[(k + 1) * 8 + 1];
                }
                unsigned long long wv;
                #pragma unroll
                for (int j = 0; j < 4; ++j) {
                    wv = (j == 0) ? wa.x : (j == 1) ? wa.y : (j == 2) ? wb.x : wb.y;
                    a[j][0] = fma2(ha.x, wv, a[j][0]);
                    a[j][1] = fma2(ha.y, wv, a[j][1]);
                    a[j][2] = fma2(hb.x, wv, a[j][2]);
                    a[j][3] = fma2(hb.y, wv, a[j][3]);
                }
                ha = ha_n; hb = hb_n; wa = wa_n; wb = wb_n;
            }
        }

        // ---- write partials: sg[wid][c][b] ----
        #pragma unroll
        for (int j = 0; j < 4; ++j) {
            int c = cq + 4 * j;
            float* dst = sg + (size_t)(wid * NC + c) * 68 + b0;
            *(ulonglong2*)(dst)     = make_ulonglong2(a[j][0], a[j][1]);
            *(ulonglong2*)(dst + 4) = make_ulonglong2(a[j][2], a[j][3]);
        }
        __syncthreads();

        // ---- pointwise: sum 8 partials + bias, update c, write h ----
        {
            float iv = bi0, fv = bi1, gv = bi2, ov = bi3;
            #pragma unroll
            for (int w = 0; w < NW; ++w) {
                const float* base = sg + (size_t)(w * NC) * 68 + pb;
                iv += base[(0 * 4 + pj) * 68];
                fv += base[(1 * 4 + pj) * 68];
                gv += base[(2 * 4 + pj) * 68];
                ov += base[(3 * 4 + pj) * 68];
            }
            creg = sigmoidf_(fv) * creg + sigmoidf_(iv) * tanhf(gv);
            float hval = sigmoidf_(ov) * tanhf(creg);
            g_hsT[((size_t)t * UU + u0 + pj) * 64 + pb] = hval;
        }

        grid_barrier();
    }
}

// ---------------------------------------------------------------------------
__global__ void out_kernel(const float* __restrict__ outW,
                           const float* __restrict__ outb,
                           float* __restrict__ y)
{
    int t  = blockIdx.x;
    int b  = threadIdx.x & 63;
    int ug = threadIdx.x >> 6;   // 0..3
    float s = 0.f;
    const float* base = g_hsT + (size_t)t * UU * BB;
    #pragma unroll 4
    for (int u = ug * 128; u < ug * 128 + 128; ++u)
        s += base[(size_t)u * 64 + b] * outW[u];
    __shared__ float red[4][64];
    red[ug][b] = s;
    __syncthreads();
    if (ug == 0) {
        float v = red[0][b] + red[1][b] + red[2][b] + red[3][b];
        v = g_coef[t] * v + g_shift[t] * g_sumW + outb[0];
        y[b * TT + t] = 1.f / (1.f + expf(-v));
    }
}

// ---------------------------------------------------------------------------
extern "C" void kernel_launch(void* const* d_in, const int* in_sizes, int n_in,
                              void* d_out, int out_size)
{
    (void)in_sizes; (void)n_in; (void)out_size;
    const float* inputs = (const float*)d_in[0];
    const float* kernel = (const float*)d_in[1];
    const float* rec    = (const float*)d_in[2];
    const float* bias   = (const float*)d_in[3];
    const float* attW   = (const float*)d_in[4];
    const float* attb   = (const float*)d_in[5];
    const float* outW   = (const float*)d_in[6];
    const float* outb   = (const float*)d_in[7];
    float* y = (float*)d_out;

    static int smem_set = 0;
    size_t smem_bytes = SMEM_FLOATS * sizeof(float);   // ~122 KB
    if (!smem_set) {
        cudaFuncSetAttribute(lstm_persist,
                             cudaFuncAttributeMaxDynamicSharedMemorySize,
                             (int)smem_bytes);
        smem_set = 1;
    }

    // pads so lstm_persist lands on ncu's capture slot (-s 5)
    pad_kernel<<<1, 32>>>();
    pad_kernel<<<1, 32>>>();
    prep_kernel<<<TT + 1, 256>>>(attW, attb, outW);
    lstm_persist<<<NBLK, NTHR, smem_bytes>>>(inputs, kernel, rec, bias);
    out_kernel<<<TT, 256>>>(outW, outb, y);
}

// round 8
// speedup vs baseline: 1.3101x; 1.1706x over previous
#include <cuda_runtime.h>
#include <math.h>

#define BB 64
#define TT 256
#define FF 64
#define UU 512
#define GG 2048      // 4*UU
#define NBLK 128
#define NTHR 256
#define CU 4         // units per block
#define NC 16        // gate-columns per block
#define NW 8         // warps (k split 8 ways)
#define KW 64        // k per warp

// ---- static device scratch (no cudaMalloc anywhere) ----
__device__ float g_hsT[(size_t)TT * UU * BB]; // all h: [(t*512+u)*64 + b]
__device__ float g_coef[TT];
__device__ float g_shift[TT];
__device__ float g_sumW;
__device__ unsigned g_cnt = 0;
__device__ volatile unsigned g_gen = 0;       // monotonic across launches

__device__ __forceinline__ float sigmoidf_(float x) { return 1.f / (1.f + expf(-x)); }

// packed fp32x2 FMA (Blackwell)
__device__ __forceinline__ unsigned long long fma2(unsigned long long a,
                                                   unsigned long long b,
                                                   unsigned long long c) {
    unsigned long long d;
    asm("fma.rn.f32x2 %0, %1, %2, %3;" : "=l"(d) : "l"(a), "l"(b), "l"(c));
    return d;
}
__device__ __forceinline__ unsigned long long pack2(float v) {
    unsigned long long p;
    unsigned u = __float_as_uint(v);
    asm("mov.b64 %0, {%1, %1};" : "=l"(p) : "r"(u));
    return p;
}

// no-op pads so ncu's fixed capture slot (-s 5) lands on lstm_persist
__global__ void pad_kernel() {}

// ---------------------------------------------------------------------------
__global__ void prep_kernel(const float* __restrict__ attW,
                            const float* __restrict__ attb,
                            const float* __restrict__ outW)
{
    __shared__ float red[256];
    int tid = threadIdx.x;
    if (blockIdx.x < TT) {
        int t = blockIdx.x;
        float s = 0.f;
        for (int j = tid; j < t; j += 256) s += attW[t * TT + j];
        red[tid] = s;
        __syncthreads();
        for (int off = 128; off > 0; off >>= 1) {
            if (tid < off) red[tid] += red[tid + off];
            __syncthreads();
        }
        if (tid == 0) {
            g_coef[t]  = (t == 0) ? 1.f : red[0];
            g_shift[t] = (t == 0) ? 0.f : attb[t];
        }
    } else {
        red[tid] = outW[tid] + outW[tid + 256];
        __syncthreads();
        for (int off = 128; off > 0; off >>= 1) {
            if (tid < off) red[tid] += red[tid + off];
            __syncthreads();
        }
        if (tid == 0) g_sumW = red[0];
    }
}

// ---------------------------------------------------------------------------
// Persistent LSTM. 128 blocks, 256 threads (8 warps, k split 8 ways).
// Warp: full 16-col x 64-batch tile for its 64 k.
// Thread: 4 cols x 8 batches = 16 f32x2 accumulators.
// w quad-packed scalar in smem (1 LDS.128 / k) + register pack2.
// h via LDG.128 from L2, register prefetch ring depth 4.
// Split grid barrier: arrive after h store; x staging + input projection
// execute between arrive and wait to hide barrier latency.
// ---------------------------------------------------------------------------
// smem (floats):
//   w4  [512][16]   =  8192 f (32 KB)  w4[k*16 + cq*4 + j] = w(col cq+4j)
//   wx4 [64][16]    =  1024 f (4 KB)
//   sx2 [64][64]    =  4096 f (16 KB)
//   sg  [8][16][68] =  8704 f (34 KB)
#define OFF_W4   0
#define OFF_WX4  (UU * NC)
#define OFF_SX   (OFF_WX4 + FF * NC)
#define OFF_SG   (OFF_SX + FF * BB)
#define SMEM_FLOATS (OFF_SG + NW * NC * 68)

__global__ void __launch_bounds__(NTHR, 1)
lstm_persist(const float* __restrict__ x,     // (B,T,F)
             const float* __restrict__ Wk,    // (F,4U)
             const float* __restrict__ Rk,    // (U,4U)
             const float* __restrict__ bias)  // (4U)
{
    extern __shared__ float smem[];
    float* w4  = smem + OFF_W4;
    float* wx4 = smem + OFF_WX4;
    float* sx2 = smem + OFF_SX;
    float* sg  = smem + OFF_SG;

    const int tid = threadIdx.x;
    const int bid = blockIdx.x;
    const int u0  = bid * CU;

    // ---- one-time weight staging (quad-packed scalar) ----
    for (int idx = tid; idx < UU * NC; idx += NTHR) {
        int k = idx >> 4, m = idx & 15;
        int c = (m >> 2) + ((m & 3) << 2);          // col for slot m
        int gcol = (c >> 2) * UU + u0 + (c & 3);
        w4[k * 16 + m] = Rk[(size_t)k * GG + gcol];
    }
    for (int idx = tid; idx < FF * NC; idx += NTHR) {
        int f = idx >> 4, m = idx & 15;
        int c = (m >> 2) + ((m & 3) << 2);
        int gcol = (c >> 2) * UU + u0 + (c & 3);
        wx4[f * 16 + m] = Wk[(size_t)f * GG + gcol];
    }

    // GEMM identity
    const int wid  = tid >> 5;        // warp 0..7 -> k range [wid*64, ..)
    const int lane = tid & 31;
    const int cq   = lane >> 3;       // 0..3: cols {cq, cq+4, cq+8, cq+12}
    const int bo   = lane & 7;        // 0..7: batches [bo*8, bo*8+8)
    const int kb   = wid * KW;
    const int b0   = bo * 8;

    // pointwise identity: unit pj, batch pb; bias preloaded
    const int pj = tid >> 6;          // 0..3
    const int pb = tid & 63;
    const float bi0 = bias[0 * UU + u0 + pj];
    const float bi1 = bias[1 * UU + u0 + pj];
    const float bi2 = bias[2 * UU + u0 + pj];
    const float bi3 = bias[3 * UU + u0 + pj];
    float creg = 0.f;

    const float4* wp  = (const float4*)w4 + (size_t)kb * 4 + cq;
    const float4* wxp = (const float4*)wx4 + (size_t)(wid * 8) * 4 + cq;

    unsigned gen_sav = 0;   // thread 0 only

    __syncthreads();

    for (int t = 0; t < TT; ++t) {
        // ---- stage x_t transposed: sx2[f*64 + b] (runs "inside" barrier) ----
        for (int i = tid; i < (BB * FF) / 4; i += NTHR) {
            int b  = i & 63;
            int f0 = (i >> 6) << 2;
            float4 xv = *(const float4*)(x + ((size_t)b * TT + t) * FF + f0);
            sx2[(f0 + 0) * 64 + b] = xv.x;
            sx2[(f0 + 1) * 64 + b] = xv.y;
            sx2[(f0 + 2) * 64 + b] = xv.z;
            sx2[(f0 + 3) * 64 + b] = xv.w;
        }
        __syncthreads();

        // accumulators: [col j][batch pair p]
        unsigned long long a[4][4];
        #pragma unroll
        for (int j = 0; j < 4; ++j)
            #pragma unroll
            for (int p = 0; p < 4; ++p) a[j][p] = 0ull;

        // ---- input projection: this warp's 8 f (also barrier filler) ----
        {
            const float* xp = sx2 + (wid * 8) * 64 + b0;
            #pragma unroll
            for (int f = 0; f < 8; ++f) {
                float4 wq = wxp[f * 4];
                ulonglong2 xa = *(const ulonglong2*)(xp + f * 64);
                ulonglong2 xb = *(const ulonglong2*)(xp + f * 64 + 4);
                unsigned long long w0 = pack2(wq.x);
                unsigned long long w1 = pack2(wq.y);
                unsigned long long w2 = pack2(wq.z);
                unsigned long long w3 = pack2(wq.w);
                a[0][0] = fma2(xa.x, w0, a[0][0]); a[0][1] = fma2(xa.y, w0, a[0][1]);
                a[0][2] = fma2(xb.x, w0, a[0][2]); a[0][3] = fma2(xb.y, w0, a[0][3]);
                a[1][0] = fma2(xa.x, w1, a[1][0]); a[1][1] = fma2(xa.y, w1, a[1][1]);
                a[1][2] = fma2(xb.x, w1, a[1][2]); a[1][3] = fma2(xb.y, w1, a[1][3]);
                a[2][0] = fma2(xa.x, w2, a[2][0]); a[2][1] = fma2(xa.y, w2, a[2][1]);
                a[2][2] = fma2(xb.x, w2, a[2][2]); a[2][3] = fma2(xb.y, w2, a[2][3]);
                a[3][0] = fma2(xa.x, w3, a[3][0]); a[3][1] = fma2(xa.y, w3, a[3][1]);
                a[3][2] = fma2(xb.x, w3, a[3][2]); a[3][3] = fma2(xb.y, w3, a[3][3]);
            }
        }

        // ---- wait: all blocks' h(t-1) visible ----
        if (t > 0) {
            if (tid == 0) {
                while (g_gen == gen_sav) { }
            }
            __syncthreads();

            // ---- recurrent projection: 64 k, h prefetch ring depth 4 ----
            const float* hp = g_hsT + ((size_t)(t - 1) * UU + kb) * BB + b0;
            ulonglong2 ha[4], hb[4];
            #pragma unroll
            for (int p = 0; p < 4; ++p) {
                ha[p] = *(const ulonglong2*)(hp + (size_t)p * 64);
                hb[p] = *(const ulonglong2*)(hp + (size_t)p * 64 + 4);
            }
            #pragma unroll 4
            for (int k = 0; k < KW; ++k) {
                float4 wq = wp[(size_t)k * 4];
                ulonglong2 ca = ha[k & 3];
                ulonglong2 cb = hb[k & 3];
                if (k + 4 < KW) {
                    const float* hn = hp + (size_t)(k + 4) * 64;
                    ha[k & 3] = *(const ulonglong2*)hn;
                    hb[k & 3] = *(const ulonglong2*)(hn + 4);
                }
                unsigned long long w0 = pack2(wq.x);
                unsigned long long w1 = pack2(wq.y);
                unsigned long long w2 = pack2(wq.z);
                unsigned long long w3 = pack2(wq.w);
                a[0][0] = fma2(ca.x, w0, a[0][0]); a[0][1] = fma2(ca.y, w0, a[0][1]);
                a[0][2] = fma2(cb.x, w0, a[0][2]); a[0][3] = fma2(cb.y, w0, a[0][3]);
                a[1][0] = fma2(ca.x, w1, a[1][0]); a[1][1] = fma2(ca.y, w1, a[1][1]);
                a[1][2] = fma2(cb.x, w1, a[1][2]); a[1][3] = fma2(cb.y, w1, a[1][3]);
                a[2][0] = fma2(ca.x, w2, a[2][0]); a[2][1] = fma2(ca.y, w2, a[2][1]);
                a[2][2] = fma2(cb.x, w2, a[2][2]); a[2][3] = fma2(cb.y, w2, a[2][3]);
                a[3][0] = fma2(ca.x, w3, a[3][0]); a[3][1] = fma2(ca.y, w3, a[3][1]);
                a[3][2] = fma2(cb.x, w3, a[3][2]); a[3][3] = fma2(cb.y, w3, a[3][3]);
            }
        }

        // ---- write partials: sg[wid][c][b] ----
        #pragma unroll
        for (int j = 0; j < 4; ++j) {
            int c = cq + 4 * j;
            float* dst = sg + (size_t)(wid * NC + c) * 68 + b0;
            *(ulonglong2*)(dst)     = make_ulonglong2(a[j][0], a[j][1]);
            *(ulonglong2*)(dst + 4) = make_ulonglong2(a[j][2], a[j][3]);
        }
        __syncthreads();

        // ---- pointwise: sum 8 partials + bias, update c, write h(t) ----
        {
            float iv = bi0, fv = bi1, gv = bi2, ov = bi3;
            #pragma unroll
            for (int w = 0; w < NW; ++w) {
                const float* base = sg + (size_t)(w * NC) * 68 + pb;
                iv += base[(0 * 4 + pj) * 68];
                fv += base[(1 * 4 + pj) * 68];
                gv += base[(2 * 4 + pj) * 68];
                ov += base[(3 * 4 + pj) * 68];
            }
            creg = sigmoidf_(fv) * creg + sigmoidf_(iv) * tanhf(gv);
            float hval = sigmoidf_(ov) * tanhf(creg);
            g_hsT[((size_t)t * UU + u0 + pj) * 64 + pb] = hval;
        }

        // ---- arrive (release h(t)); wait happens next iter after x-proj ----
        if (t + 1 < TT) {
            __threadfence();
            __syncthreads();
            if (tid == 0) {
                gen_sav = g_gen;
                if (atomicAdd(&g_cnt, 1u) == (unsigned)(NBLK - 1)) {
                    g_cnt = 0u;
                    __threadfence();
                    g_gen = gen_sav + 1u;
                }
            }
            // NOTE: no syncthreads here — threads proceed to stage sx2 for
            // t+1; the __syncthreads after staging orders sx2, and the
            // gen spin + syncthreads orders h. sg reuse is safe: sg is
            // rewritten only after the post-staging syncthreads AND the
            // gen wait, by which time all threads passed pointwise.
        }
    }
}

// ---------------------------------------------------------------------------
__global__ void out_kernel(const float* __restrict__ outW,
                           const float* __restrict__ outb,
                           float* __restrict__ y)
{
    int t  = blockIdx.x;
    int b  = threadIdx.x & 63;
    int ug = threadIdx.x >> 6;   // 0..3
    float s = 0.f;
    const float* base = g_hsT + (size_t)t * UU * BB;
    #pragma unroll 4
    for (int u = ug * 128; u < ug * 128 + 128; ++u)
        s += base[(size_t)u * 64 + b] * outW[u];
    __shared__ float red[4][64];
    red[ug][b] = s;
    __syncthreads();
    if (ug == 0) {
        float v = red[0][b] + red[1][b] + red[2][b] + red[3][b];
        v = g_coef[t] * v + g_shift[t] * g_sumW + outb[0];
        y[b * TT + t] = 1.f / (1.f + expf(-v));
    }
}

// ---------------------------------------------------------------------------
extern "C" void kernel_launch(void* const* d_in, const int* in_sizes, int n_in,
                              void* d_out, int out_size)
{
    (void)in_sizes; (void)n_in; (void)out_size;
    const float* inputs = (const float*)d_in[0];
    const float* kernel = (const float*)d_in[1];
    const float* rec    = (const float*)d_in[2];
    const float* bias   = (const float*)d_in[3];
    const float* attW   = (const float*)d_in[4];
    const float* attb   = (const float*)d_in[5];
    const float* outW   = (const float*)d_in[6];
    const float* outb   = (const float*)d_in[7];
    float* y = (float*)d_out;

    static int smem_set = 0;
    size_t smem_bytes = SMEM_FLOATS * sizeof(float);   // ~86 KB
    if (!smem_set) {
        cudaFuncSetAttribute(lstm_persist,
                             cudaFuncAttributeMaxDynamicSharedMemorySize,
                             (int)smem_bytes);
        smem_set = 1;
    }

    // pads so lstm_persist lands on ncu's capture slot (-s 5)
    pad_kernel<<<1, 32>>>();
    pad_kernel<<<1, 32>>>();
    prep_kernel<<<TT + 1, 256>>>(attW, attb, outW);
    lstm_persist<<<NBLK, NTHR, smem_bytes>>>(inputs, kernel, rec, bias);
    out_kernel<<<TT, 256>>>(outW, outb, y);
}

// round 9
// speedup vs baseline: 1.3520x; 1.0320x over previous
#include <cuda_runtime.h>
#include <math.h>

#define BB 64
#define TT 256
#define FF 64
#define UU 512
#define GG 2048      // 4*UU
#define NBLK 128
#define NTHR 512
#define CU 4         // units per block
#define NC 16        // gate-columns per block
#define NW 16        // warps (k split 16 ways)
#define KW 32        // k per warp

// ---- static device scratch (no cudaMalloc anywhere) ----
__device__ float g_hsT[(size_t)TT * UU * BB]; // all h: [(t*512+u)*64 + b]
__device__ float g_coef[TT];
__device__ float g_shift[TT];
__device__ float g_sumW;
__device__ unsigned g_cnt = 0;
__device__ volatile unsigned g_gen = 0;       // monotonic across launches

__device__ __forceinline__ float sigmoidf_(float x) { return 1.f / (1.f + expf(-x)); }

// packed fp32x2 FMA (Blackwell)
__device__ __forceinline__ unsigned long long fma2(unsigned long long a,
                                                   unsigned long long b,
                                                   unsigned long long c) {
    unsigned long long d;
    asm("fma.rn.f32x2 %0, %1, %2, %3;" : "=l"(d) : "l"(a), "l"(b), "l"(c));
    return d;
}
__device__ __forceinline__ unsigned long long pack2(float v) {
    unsigned long long p;
    unsigned u = __float_as_uint(v);
    asm("mov.b64 %0, {%1, %1};" : "=l"(p) : "r"(u));
    return p;
}

// no-op pads so ncu's fixed capture slot (-s 5) lands on lstm_persist
__global__ void pad_kernel() {}

// ---------------------------------------------------------------------------
__global__ void prep_kernel(const float* __restrict__ attW,
                            const float* __restrict__ attb,
                            const float* __restrict__ outW)
{
    __shared__ float red[256];
    int tid = threadIdx.x;
    if (blockIdx.x < TT) {
        int t = blockIdx.x;
        float s = 0.f;
        for (int j = tid; j < t; j += 256) s += attW[t * TT + j];
        red[tid] = s;
        __syncthreads();
        for (int off = 128; off > 0; off >>= 1) {
            if (tid < off) red[tid] += red[tid + off];
            __syncthreads();
        }
        if (tid == 0) {
            g_coef[t]  = (t == 0) ? 1.f : red[0];
            g_shift[t] = (t == 0) ? 0.f : attb[t];
        }
    } else {
        red[tid] = outW[tid] + outW[tid + 256];
        __syncthreads();
        for (int off = 128; off > 0; off >>= 1) {
            if (tid < off) red[tid] += red[tid + off];
            __syncthreads();
        }
        if (tid == 0) g_sumW = red[0];
    }
}

// ---------------------------------------------------------------------------
// Persistent LSTM. 128 blocks, 512 threads (16 warps = 4/SMSP, k split 16x).
// Warp: full 16-col x 64-batch tile for its 32 k.
// Thread: 4 cols x 8 batches = 16 f32x2 accumulators.
// w quad-packed scalar in smem (1 LDS.128 / k) + register pack2 (ALU pipe).
// h via LDG.128 from L2, register prefetch ring depth 2 (+3 extra warps/SMSP
// for latency cover). Split grid barrier hidden behind x staging + x-proj.
// ---------------------------------------------------------------------------
// smem (floats):
//   w4  [512][16]    =  8192 (32 KB)   w4[k*16 + cq*4 + j] = w(col cq+4j)
//   wx4 [64][16]     =  1024 (4 KB)
//   sx2 [64][64]     =  4096 (16 KB)
//   sg  [16][16][68] = 17408 (68 KB)
//   sg2 [16][68]     =  1088 (4.25 KB)
#define OFF_W4   0
#define OFF_WX4  (UU * NC)
#define OFF_SX   (OFF_WX4 + FF * NC)
#define OFF_SG   (OFF_SX + FF * BB)
#define OFF_SG2  (OFF_SG + NW * NC * 68)
#define SMEM_FLOATS (OFF_SG2 + NC * 68)

__global__ void __launch_bounds__(NTHR, 1)
lstm_persist(const float* __restrict__ x,     // (B,T,F)
             const float* __restrict__ Wk,    // (F,4U)
             const float* __restrict__ Rk,    // (U,4U)
             const float* __restrict__ bias)  // (4U)
{
    extern __shared__ float smem[];
    float* w4  = smem + OFF_W4;
    float* wx4 = smem + OFF_WX4;
    float* sx2 = smem + OFF_SX;
    float* sg  = smem + OFF_SG;
    float* sg2 = smem + OFF_SG2;

    const int tid = threadIdx.x;
    const int bid = blockIdx.x;
    const int u0  = bid * CU;

    // ---- one-time weight staging (quad-packed scalar) ----
    for (int idx = tid; idx < UU * NC; idx += NTHR) {
        int k = idx >> 4, m = idx & 15;
        int c = (m >> 2) + ((m & 3) << 2);          // col for slot m
        int gcol = (c >> 2) * UU + u0 + (c & 3);
        w4[k * 16 + m] = Rk[(size_t)k * GG + gcol];
    }
    for (int idx = tid; idx < FF * NC; idx += NTHR) {
        int f = idx >> 4, m = idx & 15;
        int c = (m >> 2) + ((m & 3) << 2);
        int gcol = (c >> 2) * UU + u0 + (c & 3);
        wx4[f * 16 + m] = Wk[(size_t)f * GG + gcol];
    }

    // GEMM identity
    const int wid  = tid >> 5;        // warp 0..15 -> k range [wid*32, ..)
    const int lane = tid & 31;
    const int cq   = lane >> 3;       // 0..3: cols {cq, cq+4, cq+8, cq+12}
    const int bo   = lane & 7;        // 0..7: batches [bo*8, bo*8+8)
    const int kb   = wid * KW;
    const int b0   = bo * 8;

    // stage-1 reduction identity: col rc, batch pair rb
    const int rc = tid & 15;          // 0..15
    const int rb = (tid >> 4) * 2;    // 0,2,...,62

    // pointwise identity (tid < 256): unit pj, batch pb; bias preloaded
    const int pj = (tid >> 6) & 3;
    const int pb = tid & 63;
    const float bi0 = bias[0 * UU + u0 + pj];
    const float bi1 = bias[1 * UU + u0 + pj];
    const float bi2 = bias[2 * UU + u0 + pj];
    const float bi3 = bias[3 * UU + u0 + pj];
    float creg = 0.f;

    const float4* wp  = (const float4*)w4 + (size_t)kb * 4 + cq;
    const float4* wxp = (const float4*)wx4 + (size_t)(wid * 4) * 4 + cq;

    unsigned gen_sav = 0;   // thread 0 only

    __syncthreads();

    for (int t = 0; t < TT; ++t) {
        // ---- stage x_t transposed (runs "inside" the split barrier) ----
        for (int i = tid; i < (BB * FF) / 4; i += NTHR) {
            int b  = i & 63;
            int f0 = (i >> 6) << 2;
            float4 xv = *(const float4*)(x + ((size_t)b * TT + t) * FF + f0);
            sx2[(f0 + 0) * 64 + b] = xv.x;
            sx2[(f0 + 1) * 64 + b] = xv.y;
            sx2[(f0 + 2) * 64 + b] = xv.z;
            sx2[(f0 + 3) * 64 + b] = xv.w;
        }
        __syncthreads();

        // accumulators: [col j][batch pair p]
        unsigned long long a[4][4];
        #pragma unroll
        for (int j = 0; j < 4; ++j)
            #pragma unroll
            for (int p = 0; p < 4; ++p) a[j][p] = 0ull;

        // ---- input projection: this warp's 4 f (barrier filler) ----
        {
            const float* xp = sx2 + (wid * 4) * 64 + b0;
            #pragma unroll
            for (int f = 0; f < 4; ++f) {
                float4 wq = wxp[f * 4];
                ulonglong2 xa = *(const ulonglong2*)(xp + f * 64);
                ulonglong2 xb = *(const ulonglong2*)(xp + f * 64 + 4);
                unsigned long long w0 = pack2(wq.x);
                unsigned long long w1 = pack2(wq.y);
                unsigned long long w2 = pack2(wq.z);
                unsigned long long w3 = pack2(wq.w);
                a[0][0] = fma2(xa.x, w0, a[0][0]); a[0][1] = fma2(xa.y, w0, a[0][1]);
                a[0][2] = fma2(xb.x, w0, a[0][2]); a[0][3] = fma2(xb.y, w0, a[0][3]);
                a[1][0] = fma2(xa.x, w1, a[1][0]); a[1][1] = fma2(xa.y, w1, a[1][1]);
                a[1][2] = fma2(xb.x, w1, a[1][2]); a[1][3] = fma2(xb.y, w1, a[1][3]);
                a[2][0] = fma2(xa.x, w2, a[2][0]); a[2][1] = fma2(xa.y, w2, a[2][1]);
                a[2][2] = fma2(xb.x, w2, a[2][2]); a[2][3] = fma2(xb.y, w2, a[2][3]);
                a[3][0] = fma2(xa.x, w3, a[3][0]); a[3][1] = fma2(xa.y, w3, a[3][1]);
                a[3][2] = fma2(xb.x, w3, a[3][2]); a[3][3] = fma2(xb.y, w3, a[3][3]);
            }
        }

        // ---- wait: all blocks' h(t-1) visible ----
        if (t > 0) {
            if (tid == 0) {
                while (g_gen == gen_sav) { }
            }
            __syncthreads();

            // ---- recurrent projection: 32 k, h prefetch ring depth 2 ----
            const float* hp = g_hsT + ((size_t)(t - 1) * UU + kb) * BB + b0;
            ulonglong2 ha[2], hb[2];
            #pragma unroll
            for (int p = 0; p < 2; ++p) {
                ha[p] = *(const ulonglong2*)(hp + (size_t)p * 64);
                hb[p] = *(const ulonglong2*)(hp + (size_t)p * 64 + 4);
            }
            #pragma unroll 4
            for (int k = 0; k < KW; ++k) {
                float4 wq = wp[(size_t)k * 4];
                ulonglong2 ca = ha[k & 1];
                ulonglong2 cb = hb[k & 1];
                if (k + 2 < KW) {
                    const float* hn = hp + (size_t)(k + 2) * 64;
                    ha[k & 1] = *(const ulonglong2*)hn;
                    hb[k & 1] = *(const ulonglong2*)(hn + 4);
                }
                unsigned long long w0 = pack2(wq.x);
                unsigned long long w1 = pack2(wq.y);
                unsigned long long w2 = pack2(wq.z);
                unsigned long long w3 = pack2(wq.w);
                a[0][0] = fma2(ca.x, w0, a[0][0]); a[0][1] = fma2(ca.y, w0, a[0][1]);
                a[0][2] = fma2(cb.x, w0, a[0][2]); a[0][3] = fma2(cb.y, w0, a[0][3]);
                a[1][0] = fma2(ca.x, w1, a[1][0]); a[1][1] = fma2(ca.y, w1, a[1][1]);
                a[1][2] = fma2(cb.x, w1, a[1][2]); a[1][3] = fma2(cb.y, w1, a[1][3]);
                a[2][0] = fma2(ca.x, w2, a[2][0]); a[2][1] = fma2(ca.y, w2, a[2][1]);
                a[2][2] = fma2(cb.x, w2, a[2][2]); a[2][3] = fma2(cb.y, w2, a[2][3]);
                a[3][0] = fma2(ca.x, w3, a[3][0]); a[3][1] = fma2(ca.y, w3, a[3][1]);
                a[3][2] = fma2(cb.x, w3, a[3][2]); a[3][3] = fma2(cb.y, w3, a[3][3]);
            }
        }

        // ---- write partials: sg[wid][c][b] ----
        #pragma unroll
        for (int j = 0; j < 4; ++j) {
            int c = cq + 4 * j;
            float* dst = sg + (size_t)(wid * NC + c) * 68 + b0;
            *(ulonglong2*)(dst)     = make_ulonglong2(a[j][0], a[j][1]);
            *(ulonglong2*)(dst + 4) = make_ulonglong2(a[j][2], a[j][3]);
        }
        __syncthreads();

        // ---- stage 1: sum 16 k-partials (all 512 threads, 2 floats each) ----
        {
            float2 s = make_float2(0.f, 0.f);
            #pragma unroll
            for (int w = 0; w < NW; ++w) {
                float2 v = *(const float2*)(sg + (size_t)(w * NC + rc) * 68 + rb);
                s.x += v.x; s.y += v.y;
            }
            *(float2*)(sg2 + rc * 68 + rb) = s;
        }
        __syncthreads();

        // ---- stage 2 pointwise (tid < 256): gates + state update ----
        if (tid < 256) {
            float iv = bi0 + sg2[(0 * 4 + pj) * 68 + pb];
            float fv = bi1 + sg2[(1 * 4 + pj) * 68 + pb];
            float gv = bi2 + sg2[(2 * 4 + pj) * 68 + pb];
            float ov = bi3 + sg2[(3 * 4 + pj) * 68 + pb];
            creg = sigmoidf_(fv) * creg + sigmoidf_(iv) * tanhf(gv);
            float hval = sigmoidf_(ov) * tanhf(creg);
            g_hsT[((size_t)t * UU + u0 + pj) * 64 + pb] = hval;
        }

        // ---- arrive (release h(t)); wait happens next iter after x-proj ----
        if (t + 1 < TT) {
            __threadfence();
            __syncthreads();
            if (tid == 0) {
                gen_sav = g_gen;
                if (atomicAdd(&g_cnt, 1u) == (unsigned)(NBLK - 1)) {
                    g_cnt = 0u;
                    __threadfence();
                    g_gen = gen_sav + 1u;
                }
            }
        }
    }
}

// ---------------------------------------------------------------------------
__global__ void out_kernel(const float* __restrict__ outW,
                           const float* __restrict__ outb,
                           float* __restrict__ y)
{
    int t  = blockIdx.x;
    int b  = threadIdx.x & 63;
    int ug = threadIdx.x >> 6;   // 0..3
    float s = 0.f;
    const float* base = g_hsT + (size_t)t * UU * BB;
    #pragma unroll 4
    for (int u = ug * 128; u < ug * 128 + 128; ++u)
        s += base[(size_t)u * 64 + b] * outW[u];
    __shared__ float red[4][64];
    red[ug][b] = s;
    __syncthreads();
    if (ug == 0) {
        float v = red[0][b] + red[1][b] + red[2][b] + red[3][b];
        v = g_coef[t] * v + g_shift[t] * g_sumW + outb[0];
        y[b * TT + t] = 1.f / (1.f + expf(-v));
    }
}

// ---------------------------------------------------------------------------
extern "C" void kernel_launch(void* const* d_in, const int* in_sizes, int n_in,
                              void* d_out, int out_size)
{
    (void)in_sizes; (void)n_in; (void)out_size;
    const float* inputs = (const float*)d_in[0];
    const float* kernel = (const float*)d_in[1];
    const float* rec    = (const float*)d_in[2];
    const float* bias   = (const float*)d_in[3];
    const float* attW   = (const float*)d_in[4];
    const float* attb   = (const float*)d_in[5];
    const float* outW   = (const float*)d_in[6];
    const float* outb   = (const float*)d_in[7];
    float* y = (float*)d_out;

    static int smem_set = 0;
    size_t smem_bytes = SMEM_FLOATS * sizeof(float);   // ~124 KB
    if (!smem_set) {
        cudaFuncSetAttribute(lstm_persist,
                             cudaFuncAttributeMaxDynamicSharedMemorySize,
                             (int)smem_bytes);
        smem_set = 1;
    }

    // pads so lstm_persist lands on ncu's capture slot (-s 5)
    pad_kernel<<<1, 32>>>();
    pad_kernel<<<1, 32>>>();
    prep_kernel<<<TT + 1, 256>>>(attW, attb, outW);
    lstm_persist<<<NBLK, NTHR, smem_bytes>>>(inputs, kernel, rec, bias);
    out_kernel<<<TT, 256>>>(outW, outb, y);
}

// round 11
// speedup vs baseline: 1.3703x; 1.0135x over previous
#include <cuda_runtime.h>
#include <math.h>

#define BB 64
#define TT 256
#define FF 64
#define UU 512
#define GG 2048      // 4*UU
#define NBLK 128
#define NTHR 512
#define CU 4         // units per block
#define NC 16        // gate-columns per block
#define NW 16        // warps (k split 16 ways)
#define KW 32        // k per warp

// ---- static device scratch (no cudaMalloc anywhere) ----
__device__ float g_hsT[(size_t)TT * UU * BB]; // all h: [(t*512+u)*64 + b]
__device__ float g_coef[TT];
__device__ float g_shift[TT];
__device__ float g_sumW;
__device__ unsigned g_cnt = 0;
__device__ unsigned g_gen = 0;                // reset every launch by prep

__device__ __forceinline__ float sigmoidf_(float x) { return 1.f / (1.f + expf(-x)); }

// packed fp32x2 FMA (Blackwell)
__device__ __forceinline__ unsigned long long fma2(unsigned long long a,
                                                   unsigned long long b,
                                                   unsigned long long c) {
    unsigned long long d;
    asm("fma.rn.f32x2 %0, %1, %2, %3;" : "=l"(d) : "l"(a), "l"(b), "l"(c));
    return d;
}
__device__ __forceinline__ unsigned long long pack2(float v) {
    unsigned long long p;
    unsigned u = __float_as_uint(v);
    asm("mov.b64 %0, {%1, %1};" : "=l"(p) : "r"(u));
    return p;
}
__device__ __forceinline__ unsigned ld_acq_gpu(const unsigned* p) {
    unsigned v;
    asm volatile("ld.acquire.gpu.global.u32 %0, [%1];" : "=r"(v) : "l"(p) : "memory");
    return v;
}
__device__ __forceinline__ unsigned atom_add_rel_gpu(unsigned* p, unsigned v) {
    unsigned old;
    asm volatile("atom.release.gpu.global.add.u32 %0, [%1], %2;"
                 : "=r"(old) : "l"(p), "r"(v) : "memory");
    return old;
}
__device__ __forceinline__ void st_rel_gpu(unsigned* p, unsigned v) {
    asm volatile("st.release.gpu.global.u32 [%0], %1;" :: "l"(p), "r"(v) : "memory");
}

// no-op pads so ncu's fixed capture slot (-s 5) lands on lstm_persist
__global__ void pad_kernel() {}

// ---------------------------------------------------------------------------
// prep: coef/shift/sumW; block TT also resets the grid-barrier state so the
// generation at LSTM step t is exactly t on every launch/replay.
// ---------------------------------------------------------------------------
__global__ void prep_kernel(const float* __restrict__ attW,
                            const float* __restrict__ attb,
                            const float* __restrict__ outW)
{
    __shared__ float red[256];
    int tid = threadIdx.x;
    if (blockIdx.x < TT) {
        int t = blockIdx.x;
        float s = 0.f;
        for (int j = tid; j < t; j += 256) s += attW[t * TT + j];
        red[tid] = s;
        __syncthreads();
        for (int off = 128; off > 0; off >>= 1) {
            if (tid < off) red[tid] += red[tid + off];
            __syncthreads();
        }
        if (tid == 0) {
            g_coef[t]  = (t == 0) ? 1.f : red[0];
            g_shift[t] = (t == 0) ? 0.f : attb[t];
        }
    } else {
        if (tid == 0) { g_cnt = 0u; g_gen = 0u; }
        red[tid] = outW[tid] + outW[tid + 256];
        __syncthreads();
        for (int off = 128; off > 0; off >>= 1) {
            if (tid < off) red[tid] += red[tid + off];
            __syncthreads();
        }
        if (tid == 0) g_sumW = red[0];
    }
}

// ---------------------------------------------------------------------------
// Persistent LSTM. 128 blocks, 512 threads (16 warps = 4/SMSP, k split 16x).
// Warp: full 16-col x 64-batch tile for its 32 k.
// Thread: 4 cols x 8 batches = 16 f32x2 accumulators.
// w quad-packed scalar in smem (1 LDS.128 / k) + register pack2 (ALU pipe).
// h via LDG.128 from L2 with register prefetch ring depth 4.
// Grid barrier: release-atomic arrive / acquire-load wait; generation at step
// t is exactly t (state reset each launch). Arrive is split from wait; x
// staging + input projection execute in between to hide barrier latency.
// ---------------------------------------------------------------------------
// smem (floats):
//   w4  [512][16]    =  8192 (32 KB)   w4[k*16 + cq*4 + j] = w(col cq+4j)
//   wx4 [64][16]     =  1024 (4 KB)
//   sx2 [64][64]     =  4096 (16 KB)
//   sg  [16][16][68] = 17408 (68 KB)
//   sg2 [16][68]     =  1088 (4.25 KB)
#define OFF_W4   0
#define OFF_WX4  (UU * NC)
#define OFF_SX   (OFF_WX4 + FF * NC)
#define OFF_SG   (OFF_SX + FF * BB)
#define OFF_SG2  (OFF_SG + NW * NC * 68)
#define SMEM_FLOATS (OFF_SG2 + NC * 68)

__global__ void __launch_bounds__(NTHR, 1)
lstm_persist(const float* __restrict__ x,     // (B,T,F)
             const float* __restrict__ Wk,    // (F,4U)
             const float* __restrict__ Rk,    // (U,4U)
             const float* __restrict__ bias)  // (4U)
{
    extern __shared__ float smem[];
    float* w4  = smem + OFF_W4;
    float* wx4 = smem + OFF_WX4;
    float* sx2 = smem + OFF_SX;
    float* sg  = smem + OFF_SG;
    float* sg2 = smem + OFF_SG2;

    const int tid = threadIdx.x;
    const int bid = blockIdx.x;
    const int u0  = bid * CU;

    // ---- one-time weight staging (quad-packed scalar) ----
    for (int idx = tid; idx < UU * NC; idx += NTHR) {
        int k = idx >> 4, m = idx & 15;
        int c = (m >> 2) + ((m & 3) << 2);          // col for slot m
        int gcol = (c >> 2) * UU + u0 + (c & 3);
        w4[k * 16 + m] = Rk[(size_t)k * GG + gcol];
    }
    for (int idx = tid; idx < FF * NC; idx += NTHR) {
        int f = idx >> 4, m = idx & 15;
        int c = (m >> 2) + ((m & 3) << 2);
        int gcol = (c >> 2) * UU + u0 + (c & 3);
        wx4[f * 16 + m] = Wk[(size_t)f * GG + gcol];
    }

    // GEMM identity
    const int wid  = tid >> 5;        // warp 0..15 -> k range [wid*32, ..)
    const int lane = tid & 31;
    const int cq   = lane >> 3;       // 0..3: cols {cq, cq+4, cq+8, cq+12}
    const int bo   = lane & 7;        // 0..7: batches [bo*8, bo*8+8)
    const int kb   = wid * KW;
    const int b0   = bo * 8;

    // stage-1 reduction identity: col rc, batch pair rb
    const int rc = tid & 15;          // 0..15
    const int rb = (tid >> 4) * 2;    // 0,2,...,62

    // pointwise identity (tid < 256): unit pj, batch pb; bias preloaded
    const int pj = (tid >> 6) & 3;
    const int pb = tid & 63;
    const float bi0 = bias[0 * UU + u0 + pj];
    const float bi1 = bias[1 * UU + u0 + pj];
    const float bi2 = bias[2 * UU + u0 + pj];
    const float bi3 = bias[3 * UU + u0 + pj];
    float creg = 0.f;

    const float4* wp  = (const float4*)w4 + (size_t)kb * 4 + cq;
    const float4* wxp = (const float4*)wx4 + (size_t)(wid * 4) * 4 + cq;

    __syncthreads();

    for (int t = 0; t < TT; ++t) {
        // ---- stage x_t transposed (runs "inside" the split barrier) ----
        for (int i = tid; i < (BB * FF) / 4; i += NTHR) {
            int b  = i & 63;
            int f0 = (i >> 6) << 2;
            float4 xv = *(const float4*)(x + ((size_t)b * TT + t) * FF + f0);
            sx2[(f0 + 0) * 64 + b] = xv.x;
            sx2[(f0 + 1) * 64 + b] = xv.y;
            sx2[(f0 + 2) * 64 + b] = xv.z;
            sx2[(f0 + 3) * 64 + b] = xv.w;
        }
        __syncthreads();

        // accumulators: [col j][batch pair p]
        unsigned long long a[4][4];
        #pragma unroll
        for (int j = 0; j < 4; ++j)
            #pragma unroll
            for (int p = 0; p < 4; ++p) a[j][p] = 0ull;

        // ---- input projection: this warp's 4 f (barrier filler) ----
        {
            const float* xp = sx2 + (wid * 4) * 64 + b0;
            #pragma unroll
            for (int f = 0; f < 4; ++f) {
                float4 wq = wxp[f * 4];
                ulonglong2 xa = *(const ulonglong2*)(xp + f * 64);
                ulonglong2 xb = *(const ulonglong2*)(xp + f * 64 + 4);
                unsigned long long w0 = pack2(wq.x);
                unsigned long long w1 = pack2(wq.y);
                unsigned long long w2 = pack2(wq.z);
                unsigned long long w3 = pack2(wq.w);
                a[0][0] = fma2(xa.x, w0, a[0][0]); a[0][1] = fma2(xa.y, w0, a[0][1]);
                a[0][2] = fma2(xb.x, w0, a[0][2]); a[0][3] = fma2(xb.y, w0, a[0][3]);
                a[1][0] = fma2(xa.x, w1, a[1][0]); a[1][1] = fma2(xa.y, w1, a[1][1]);
                a[1][2] = fma2(xb.x, w1, a[1][2]); a[1][3] = fma2(xb.y, w1, a[1][3]);
                a[2][0] = fma2(xa.x, w2, a[2][0]); a[2][1] = fma2(xa.y, w2, a[2][1]);
                a[2][2] = fma2(xb.x, w2, a[2][2]); a[2][3] = fma2(xb.y, w2, a[2][3]);
                a[3][0] = fma2(xa.x, w3, a[3][0]); a[3][1] = fma2(xa.y, w3, a[3][1]);
                a[3][2] = fma2(xb.x, w3, a[3][2]); a[3][3] = fma2(xb.y, w3, a[3][3]);
            }
        }

        // ---- wait: generation must reach t (h(t-1) released) ----
        if (t > 0) {
            if (tid == 0) {
                while (ld_acq_gpu(&g_gen) < (unsigned)t) { }
            }
            __syncthreads();

            // ---- recurrent projection: 32 k, h prefetch ring depth 4 ----
            const float* hp = g_hsT + ((size_t)(t - 1) * UU + kb) * BB + b0;
            ulonglong2 ha[4], hb[4];
            #pragma unroll
            for (int p = 0; p < 4; ++p) {
                ha[p] = *(const ulonglong2*)(hp + (size_t)p * 64);
                hb[p] = *(const ulonglong2*)(hp + (size_t)p * 64 + 4);
            }
            const float* hn = hp + 4 * 64;
            #pragma unroll 4
            for (int k = 0; k < KW; ++k) {
                float4 wq = wp[(size_t)k * 4];
                ulonglong2 ca = ha[k & 3];
                ulonglong2 cb = hb[k & 3];
                if (k + 4 < KW) {
                    ha[k & 3] = *(const ulonglong2*)hn;
                    hb[k & 3] = *(const ulonglong2*)(hn + 4);
                    hn += 64;
                }
                unsigned long long w0 = pack2(wq.x);
                unsigned long long w1 = pack2(wq.y);
                unsigned long long w2 = pack2(wq.z);
                unsigned long long w3 = pack2(wq.w);
                a[0][0] = fma2(ca.x, w0, a[0][0]); a[0][1] = fma2(ca.y, w0, a[0][1]);
                a[0][2] = fma2(cb.x, w0, a[0][2]); a[0][3] = fma2(cb.y, w0, a[0][3]);
                a[1][0] = fma2(ca.x, w1, a[1][0]); a[1][1] = fma2(ca.y, w1, a[1][1]);
                a[1][2] = fma2(cb.x, w1, a[1][2]); a[1][3] = fma2(cb.y, w1, a[1][3]);
                a[2][0] = fma2(ca.x, w2, a[2][0]); a[2][1] = fma2(ca.y, w2, a[2][1]);
                a[2][2] = fma2(cb.x, w2, a[2][2]); a[2][3] = fma2(cb.y, w2, a[2][3]);
                a[3][0] = fma2(ca.x, w3, a[3][0]); a[3][1] = fma2(ca.y, w3, a[3][1]);
                a[3][2] = fma2(cb.x, w3, a[3][2]); a[3][3] = fma2(cb.y, w3, a[3][3]);
            }
        }

        // ---- write partials: sg[wid][c][b] ----
        #pragma unroll
        for (int j = 0; j < 4; ++j) {
            int c = cq + 4 * j;
            float* dst = sg + (size_t)(wid * NC + c) * 68 + b0;
            *(ulonglong2*)(dst)     = make_ulonglong2(a[j][0], a[j][1]);
            *(ulonglong2*)(dst + 4) = make_ulonglong2(a[j][2], a[j][3]);
        }
        __syncthreads();

        // ---- stage 1: sum 16 k-partials (all 512 threads, 2 floats each) ----
        {
            float2 s = make_float2(0.f, 0.f);
            #pragma unroll
            for (int w = 0; w < NW; ++w) {
                float2 v = *(const float2*)(sg + (size_t)(w * NC + rc) * 68 + rb);
                s.x += v.x; s.y += v.y;
            }
            *(float2*)(sg2 + rc * 68 + rb) = s;
        }
        __syncthreads();

        // ---- stage 2 pointwise (tid < 256): gates + state update ----
        if (tid < 256) {
            float iv = bi0 + sg2[(0 * 4 + pj) * 68 + pb];
            float fv = bi1 + sg2[(1 * 4 + pj) * 68 + pb];
            float gv = bi2 + sg2[(2 * 4 + pj) * 68 + pb];
            float ov = bi3 + sg2[(3 * 4 + pj) * 68 + pb];
            creg = sigmoidf_(fv) * creg + sigmoidf_(iv) * tanhf(gv);
            float hval = sigmoidf_(ov) * tanhf(creg);
            g_hsT[((size_t)t * UU + u0 + pj) * 64 + pb] = hval;
        }

        // ---- arrive: release h(t). h-stores happen-before bar.sync, which
        //      happens-before tid0's release atom; waiters acquire. ----
        if (t + 1 < TT) {
            __syncthreads();
            if (tid == 0) {
                unsigned old = atom_add_rel_gpu(&g_cnt, 1u);
                if (old == (unsigned)(NBLK - 1)) {
                    g_cnt = 0u;                       // ordered before release
                    st_rel_gpu(&g_gen, (unsigned)(t + 1));
                }
            }
        }
    }
}

// ---------------------------------------------------------------------------
__global__ void out_kernel(const float* __restrict__ outW,
                           const float* __restrict__ outb,
                           float* __restrict__ y)
{
    int t  = blockIdx.x;
    int b  = threadIdx.x & 63;
    int ug = threadIdx.x >> 6;   // 0..3
    float s = 0.f;
    const float* base = g_hsT + (size_t)t * UU * BB;
    #pragma unroll 4
    for (int u = ug * 128; u < ug * 128 + 128; ++u)
        s += base[(size_t)u * 64 + b] * outW[u];
    __shared__ float red[4][64];
    red[ug][b] = s;
    __syncthreads();
    if (ug == 0) {
        float v = red[0][b] + red[1][b] + red[2][b] + red[3][b];
        v = g_coef[t] * v + g_shift[t] * g_sumW + outb[0];
        y[b * TT + t] = 1.f / (1.f + expf(-v));
    }
}

// ---------------------------------------------------------------------------
extern "C" void kernel_launch(void* const* d_in, const int* in_sizes, int n_in,
                              void* d_out, int out_size)
{
    (void)in_sizes; (void)n_in; (void)out_size;
    const float* inputs = (const float*)d_in[0];
    const float* kernel = (const float*)d_in[1];
    const float* rec    = (const float*)d_in[2];
    const float* bias   = (const float*)d_in[3];
    const float* attW   = (const float*)d_in[4];
    const float* attb   = (const float*)d_in[5];
    const float* outW   = (const float*)d_in[6];
    const float* outb   = (const float*)d_in[7];
    float* y = (float*)d_out;

    static int smem_set = 0;
    size_t smem_bytes = SMEM_FLOATS * sizeof(float);   // ~124 KB
    if (!smem_set) {
        cudaFuncSetAttribute(lstm_persist,
                             cudaFuncAttributeMaxDynamicSharedMemorySize,
                             (int)smem_bytes);
        smem_set = 1;
    }

    // pads so lstm_persist lands on ncu's capture slot (-s 5)
    pad_kernel<<<1, 32>>>();
    pad_kernel<<<1, 32>>>();
    prep_kernel<<<TT + 1, 256>>>(attW, attb, outW);    // also resets barrier state
    lstm_persist<<<NBLK, NTHR, smem_bytes>>>(inputs, kernel, rec, bias);
    out_kernel<<<TT, 256>>>(outW, outb, y);
}